// round 12
// baseline (speedup 1.0000x reference)
#include <cuda_runtime.h>
#include <cstdint>

#define HID   64
#define NVEC  16384
#define NB    8192

// bot/top (s-product + eta*(h@W2+b2)): g_bt[n][k], k<8192 bot, >=8192 top
__device__ float g_bt[128 * NVEC];   // 8 MB

// ---- packed fp32x2 helpers ----
__device__ __forceinline__ unsigned long long pack2(float x, float y) {
    unsigned long long d;
    asm("mov.b64 %0, {%1, %2};" : "=l"(d) : "f"(x), "f"(y));
    return d;
}
__device__ __forceinline__ void unpack2(unsigned long long d, float& x, float& y) {
    asm("mov.b64 {%0, %1}, %2;" : "=f"(x), "=f"(y) : "l"(d));
}
__device__ __forceinline__ unsigned long long fma2(unsigned long long a,
                                                   unsigned long long b,
                                                   unsigned long long c) {
    unsigned long long d;
    asm("fma.rn.f32x2 %0, %1, %2, %3;" : "=l"(d) : "l"(a), "l"(b), "l"(c));
    return d;
}

__device__ __forceinline__ void cp_async16(uint32_t dst, const void* src) {
    asm volatile("cp.async.cg.shared.global [%0], [%1], 16;" :: "r"(dst), "l"(src));
}

// ---------------------------------------------------------------------------
// Kernel A: fused GEMM + bot/top build.
// grid = (16 slabs, 8 sample-groups) = 128 blocks (one wave), 512 threads.
// tid>>8 selects the 8-sample half; tid&255 selects k4 = slab*1024 + (tid&255)*4.
// Each thread: 4 consecutive k for 8 samples (1:4 LDS:FFMA2 ratio, 16 warps/SM).
// ---------------------------------------------------------------------------
__global__ void __launch_bounds__(512) fused_gemm_build(
    const int*   __restrict__ cfg,
    const float* __restrict__ A,
    const float* __restrict__ W1,
    const float* __restrict__ b1,
    const float* __restrict__ W2,
    const float* __restrict__ b2)
{
    __shared__ unsigned long long sh_hd[16 * HID];  // 8 KB, {h,h} duplicated
    __shared__ float sh_s[16 * 512];                // 32 KB: per sample, 2 slices x 256
    __shared__ int   sh_c[32];

    const int tid    = threadIdx.x;
    const int slab   = blockIdx.x;      // 0..15
    const int n0     = blockIdx.y * 16;
    const int xx     = slab & 7;
    const int isTop  = slab >> 3;
    const int ybase  = isTop * 2;       // bot: y=0,1 ; top: y=2,3
    const int shalf  = tid >> 8;        // 0: samples 0..7, 1: samples 8..15
    const int tk     = tid & 255;
    const int k4     = slab * 1024 + tk * 4;
    const int sbase  = shalf * 8;

    if (tid < 32) {
        const int s = tid >> 1, sl = tid & 1;
        sh_c[tid] = cfg[(n0 + s) * 32 + xx * 4 + ybase + sl];
    }
    __syncthreads();

    // Gather the two needed slices per sample (8192 floats, 16/thread)
    const float2* A2 = (const float2*)A;
    #pragma unroll
    for (int q = 0; q < 16; q++) {
        const int m   = q * 512 + tid;
        const int s   = m >> 9;
        const int sl  = (m >> 8) & 1;
        const int idx = m & 255;
        const float2 a = A2[(xx * 4 + ybase + sl) * 256 + idx];
        sh_s[m] = sh_c[(s << 1) | sl] ? a.y : a.x;
    }

    // H = relu(cfg@W1+b1), 1024 outputs, 2/thread, stored duplicated
    #pragma unroll
    for (int q = 0; q < 2; q++) {
        const int m  = q * 512 + tid;
        const int ln = m >> 6;
        const int o  = m & 63;
        float acc = b1[o];
        const int* crow = cfg + (n0 + ln) * 32;
        #pragma unroll
        for (int i = 0; i < 32; i++)
            acc = fmaf((float)crow[i], W1[i * HID + o], acc);
        const float h = fmaxf(acc, 0.0f);
        sh_hd[ln * HID + o] = pack2(h, h);
    }
    __syncthreads();

    // GEMM: acc[s*2+p], p = k-pair within k4
    unsigned long long acc[16];
    #pragma unroll
    for (int q = 0; q < 16; q++) acc[q] = 0ull;

    #pragma unroll 4
    for (int jq = 0; jq < 16; jq++) {
        const int j0 = jq * 4;
        const float4 w0 = *(const float4*)(W2 + (j0 + 0) * NVEC + k4);
        const float4 w1 = *(const float4*)(W2 + (j0 + 1) * NVEC + k4);
        const float4 w2 = *(const float4*)(W2 + (j0 + 2) * NVEC + k4);
        const float4 w3 = *(const float4*)(W2 + (j0 + 3) * NVEC + k4);
        const unsigned long long w0lo = pack2(w0.x, w0.y), w0hi = pack2(w0.z, w0.w);
        const unsigned long long w1lo = pack2(w1.x, w1.y), w1hi = pack2(w1.z, w1.w);
        const unsigned long long w2lo = pack2(w2.x, w2.y), w2hi = pack2(w2.z, w2.w);
        const unsigned long long w3lo = pack2(w3.x, w3.y), w3hi = pack2(w3.z, w3.w);

        #pragma unroll
        for (int s = 0; s < 8; s++) {
            const int sn = sbase + s;
            const ulonglong2 hd01 = *(const ulonglong2*)(sh_hd + sn * HID + j0);
            const ulonglong2 hd23 = *(const ulonglong2*)(sh_hd + sn * HID + j0 + 2);
            unsigned long long a0 = acc[s * 2 + 0];
            unsigned long long a1 = acc[s * 2 + 1];
            a0 = fma2(hd01.x, w0lo, a0);  a1 = fma2(hd01.x, w0hi, a1);
            a0 = fma2(hd01.y, w1lo, a0);  a1 = fma2(hd01.y, w1hi, a1);
            a0 = fma2(hd23.x, w2lo, a0);  a1 = fma2(hd23.x, w2hi, a1);
            a0 = fma2(hd23.y, w3lo, a0);  a1 = fma2(hd23.y, w3hi, a1);
            acc[s * 2 + 0] = a0;
            acc[s * 2 + 1] = a1;
        }
    }

    // Epilogue: add s-product, write bt (4 k per thread, 8 samples)
    const int idx = tk * 4;
    const int i  = idx >> 6;
    const int j  = (idx >> 2) & 15;
    const int l = i >> 2, L = i & 3, r = j >> 2, R = j & 3;
    const float4 bk  = *(const float4*)(b2 + k4);
    const float  eta = 0.001f;

    if (!isTop) {
        #pragma unroll
        for (int s = 0; s < 8; s++) {
            const int sn = sbase + s;
            float4 cr;
            unpack2(acc[s * 2 + 0], cr.x, cr.y);
            unpack2(acc[s * 2 + 1], cr.z, cr.w);
            cr.x += bk.x; cr.y += bk.y; cr.z += bk.z; cr.w += bk.w;

            const float* sa = sh_s + sn * 512;        // s0 slice
            const float* sb = sh_s + sn * 512 + 256;  // s1 slice
            const float4  a0 = *(const float4*)(sa + l * 64 + r * 16);
            const float4* b4 = (const float4*)(sb + L * 64 + R * 16);
            const float4 b0 = b4[0], b1v = b4[1], b2v = b4[2], b3v = b4[3];
            float4 o4;
            o4.x = fmaf(a0.x, b0.x, fmaf(a0.y, b1v.x, fmaf(a0.z, b2v.x, fmaf(a0.w, b3v.x, eta * cr.x))));
            o4.y = fmaf(a0.x, b0.y, fmaf(a0.y, b1v.y, fmaf(a0.z, b2v.y, fmaf(a0.w, b3v.y, eta * cr.y))));
            o4.z = fmaf(a0.x, b0.z, fmaf(a0.y, b1v.z, fmaf(a0.z, b2v.z, fmaf(a0.w, b3v.z, eta * cr.z))));
            o4.w = fmaf(a0.x, b0.w, fmaf(a0.y, b1v.w, fmaf(a0.z, b2v.w, fmaf(a0.w, b3v.w, eta * cr.w))));
            *(float4*)(g_bt + (n0 + sn) * NVEC + k4) = o4;
        }
    } else {
        #pragma unroll
        for (int s = 0; s < 8; s++) {
            const int sn = sbase + s;
            float4 cr;
            unpack2(acc[s * 2 + 0], cr.x, cr.y);
            unpack2(acc[s * 2 + 1], cr.z, cr.w);
            cr.x += bk.x; cr.y += bk.y; cr.z += bk.z; cr.w += bk.w;

            const float* sa = sh_s + sn * 512;        // s2 slice
            const float* sb = sh_s + sn * 512 + 256;  // s3 slice
            const float4* c4 = (const float4*)(sa + l * 64 + r * 16);
            const float4 c0 = c4[0], c1 = c4[1], c2 = c4[2], c3 = c4[3];
            const float e0 = sb[L * 64 + R * 16 + 0];
            const float e1 = sb[L * 64 + R * 16 + 4];
            const float e2 = sb[L * 64 + R * 16 + 8];
            const float e3 = sb[L * 64 + R * 16 + 12];
            float4 o4;
            o4.x = fmaf(c0.x, e0, fmaf(c0.y, e1, fmaf(c0.z, e2, fmaf(c0.w, e3, eta * cr.x))));
            o4.y = fmaf(c1.x, e0, fmaf(c1.y, e1, fmaf(c1.z, e2, fmaf(c1.w, e3, eta * cr.y))));
            o4.z = fmaf(c2.x, e0, fmaf(c2.y, e1, fmaf(c2.z, e2, fmaf(c2.w, e3, eta * cr.z))));
            o4.w = fmaf(c3.x, e0, fmaf(c3.y, e1, fmaf(c3.z, e2, fmaf(c3.w, e3, eta * cr.w))));
            *(float4*)(g_bt + (n0 + sn) * NVEC + k4) = o4;
        }
    }
}

// ---------------------------------------------------------------------------
// Kernel B: scan only. 128 blocks x 512 threads, 4-deep cp.async pipeline.
// FFMA2 datapath; v stored duplicated {v,v}; 1 block barrier per x.
// ---------------------------------------------------------------------------
__global__ void __launch_bounds__(512) scan_kernel(float* __restrict__ out)
{
    __shared__ float buf[4][2048];                    // 32 KB: 4 tiles [bot|top]
    __shared__ float sh_t[1024];
    __shared__ unsigned long long sh_vd[2][256];      // duplicated v, ping-pong

    const int n   = blockIdx.x;
    const int tid = threadIdx.x;
    const float* src = g_bt + n * NVEC;

    const int half = tid >> 8;
    const int e4   = (tid & 255) * 4;
    const uint32_t dst_off = (uint32_t)__cvta_generic_to_shared(
        &buf[0][half * 1024 + e4]);

    // Prefetch tiles 0..3 (one commit group each)
    #pragma unroll
    for (int p = 0; p < 4; p++) {
        cp_async16(dst_off + p * 2048 * 4, src + p * 1024 + half * 8192 + e4);
        asm volatile("cp.async.commit_group;");
    }

    if (tid < 256) {
        const float v = (tid == 0) ? 1.0f : 0.0f;
        sh_vd[0][tid] = pack2(v, v);
    }

    const int w    = tid >> 5;
    const int lane = tid & 31;
    const int I15  = lane & 15;        // I (step1) / J (step2)
    const int ih   = lane >> 4;        // i-half / I-half

    #pragma unroll 1
    for (int x = 0; x < 8; x++) {
        asm volatile("cp.async.wait_group 3;");
        __syncthreads();   // tile x ready; prev v visible

        const float* bt = buf[x & 3];
        const float* tp = buf[x & 3] + 1024;
        const unsigned long long* vcur  = sh_vd[x & 1];
        unsigned long long*       vnext = sh_vd[(x & 1) ^ 1];

        // step1: t[I,U] = sum_i v[i,I] * bot[i*64 + w*4 + U]
        {
            unsigned long long a01 = 0ull, a23 = 0ull;
            #pragma unroll
            for (int it = 0; it < 8; it++) {
                const int i = ih * 8 + it;
                const ulonglong2 bb = *(const ulonglong2*)(bt + i * 64 + w * 4);
                const unsigned long long vv = vcur[i * 16 + I15];
                a01 = fma2(bb.x, vv, a01);
                a23 = fma2(bb.y, vv, a23);
            }
            float t0, t1, t2, t3;
            unpack2(a01, t0, t1);
            unpack2(a23, t2, t3);
            t0 += __shfl_xor_sync(0xffffffffu, t0, 16);
            t1 += __shfl_xor_sync(0xffffffffu, t1, 16);
            t2 += __shfl_xor_sync(0xffffffffu, t2, 16);
            t3 += __shfl_xor_sync(0xffffffffu, t3, 16);
            if (lane < 16)
                *(float4*)(sh_t + w * 64 + I15 * 4) = make_float4(t0, t1, t2, t3);
        }
        __syncwarp();

        // step2: v'[w,J] = sum_{I,U} t[I,U] * top[I*64 + J*4 + U]
        {
            unsigned long long c01 = 0ull, c23 = 0ull;
            #pragma unroll
            for (int it = 0; it < 8; it++) {
                const int I = ih * 8 + it;
                const ulonglong2 tt = *(const ulonglong2*)(sh_t + w * 64 + I * 4);
                const ulonglong2 pp = *(const ulonglong2*)(tp + I * 64 + I15 * 4);
                c01 = fma2(tt.x, pp.x, c01);
                c23 = fma2(tt.y, pp.y, c23);
            }
            float s0, s1, s2, s3;
            unpack2(c01, s0, s1);
            unpack2(c23, s2, s3);
            float nv = (s0 + s1) + (s2 + s3);
            nv += __shfl_xor_sync(0xffffffffu, nv, 16);
            if (lane < 16) vnext[w * 16 + I15] = pack2(nv, nv);
        }
        __syncthreads();   // done reading buf[x&3] and vcur

        // Refill slot (x&3) with tile x+4
        if (x < 4) {
            cp_async16(dst_off + (x & 3) * 2048 * 4,
                       src + (x + 4) * 1024 + half * 8192 + e4);
        }
        asm volatile("cp.async.commit_group;");   // empty group keeps count aligned
    }

    if (tid == 0) {
        float a, b;
        unpack2(sh_vd[0][0], a, b);   // x=7 wrote sh_vd[0]
        out[n] = a;
    }
}

// ---------------------------------------------------------------------------
extern "C" void kernel_launch(void* const* d_in, const int* in_sizes, int n_in,
                              void* d_out, int out_size)
{
    const int*   cfg = (const int*)  d_in[0];
    const float* A   = (const float*)d_in[1];
    const float* W1  = (const float*)d_in[2];
    const float* b1  = (const float*)d_in[3];
    const float* W2  = (const float*)d_in[4];
    const float* b2  = (const float*)d_in[5];
    float* out = (float*)d_out;

    fused_gemm_build<<<dim3(16, 8), 512>>>(cfg, A, W1, b1, W2, b2);
    scan_kernel<<<128, 512>>>(out);
}

// round 13
// speedup vs baseline: 1.3535x; 1.3535x over previous
#include <cuda_runtime.h>
#include <cstdint>

#define HID   64
#define NVEC  16384
#define NB    8192

// bot/top (s-product + eta*(h@W2+b2)): g_bt[n][k], k<8192 bot, >=8192 top
__device__ float g_bt[128 * NVEC];   // 8 MB

// ---- packed fp32x2 helpers ----
__device__ __forceinline__ unsigned long long pack2(float x, float y) {
    unsigned long long d;
    asm("mov.b64 %0, {%1, %2};" : "=l"(d) : "f"(x), "f"(y));
    return d;
}
__device__ __forceinline__ void unpack2(unsigned long long d, float& x, float& y) {
    asm("mov.b64 {%0, %1}, %2;" : "=f"(x), "=f"(y) : "l"(d));
}
__device__ __forceinline__ unsigned long long fma2(unsigned long long a,
                                                   unsigned long long b,
                                                   unsigned long long c) {
    unsigned long long d;
    asm("fma.rn.f32x2 %0, %1, %2, %3;" : "=l"(d) : "l"(a), "l"(b), "l"(c));
    return d;
}

__device__ __forceinline__ void cp_async16(uint32_t dst, const void* src) {
    asm volatile("cp.async.cg.shared.global [%0], [%1], 16;" :: "r"(dst), "l"(src));
}
#define COMMIT() asm volatile("cp.async.commit_group;")
#define WAITG(N) asm volatile("cp.async.wait_group " #N ";")

// ---------------------------------------------------------------------------
// Kernel A: fused GEMM + bot/top build, W2 staged via cp.async double buffer.
// grid = (16 slabs, 8 sample-groups) = 128 blocks (one wave), 512 threads.
// tid>>8 = 8-sample half; tk=tid&255 -> k4 = slab*1024 + tk*4 (4 k / thread).
// Dynamic smem (floats): w_buf[2][4096] | sh_s[8192] | sh_hd (2048 f = 1024 u64)
// ---------------------------------------------------------------------------
#define A_SMEM_FLOATS (8192 + 8192 + 2048)

__global__ void __launch_bounds__(512) fused_gemm_build(
    const int*   __restrict__ cfg,
    const float* __restrict__ A,
    const float* __restrict__ W1,
    const float* __restrict__ b1,
    const float* __restrict__ W2,
    const float* __restrict__ b2)
{
    extern __shared__ float sm[];
    float* w_buf = sm;                                   // 2 stages x 4096
    float* sh_s  = sm + 8192;                            // 16 samples x 512
    unsigned long long* sh_hd = (unsigned long long*)(sm + 16384);  // 16 x 64
    __shared__ int sh_c[32];

    const int tid    = threadIdx.x;
    const int slab   = blockIdx.x;      // 0..15
    const int n0     = blockIdx.y * 16;
    const int xx     = slab & 7;
    const int isTop  = slab >> 3;
    const int ybase  = isTop * 2;       // bot: y=0,1 ; top: y=2,3
    const int shalf  = tid >> 8;
    const int tk     = tid & 255;
    const int k4     = slab * 1024 + tk * 4;
    const int sbase  = shalf * 8;

    // --- stage W2 rows 0..3 into w_buf[0] (each thread 8 floats = 2 cp16) ---
    {
        const int f0  = tid * 8;                 // 0..4088
        const int row = f0 >> 10;
        const int col = f0 & 1023;
        const float* srcw = W2 + row * NVEC + slab * 1024 + col;
        const uint32_t d = (uint32_t)__cvta_generic_to_shared(w_buf + f0);
        cp_async16(d, srcw);
        cp_async16(d + 16, srcw + 4);
    }
    COMMIT();

    if (tid < 32) {
        const int s = tid >> 1, sl = tid & 1;
        sh_c[tid] = cfg[(n0 + s) * 32 + xx * 4 + ybase + sl];
    }
    __syncthreads();

    // Gather the two needed A-slices per sample (8192 floats, 16/thread)
    const float2* A2 = (const float2*)A;
    #pragma unroll
    for (int q = 0; q < 16; q++) {
        const int m   = q * 512 + tid;
        const int s   = m >> 9;
        const int sl  = (m >> 8) & 1;
        const int idx = m & 255;
        const float2 a = A2[(xx * 4 + ybase + sl) * 256 + idx];
        sh_s[m] = sh_c[(s << 1) | sl] ? a.y : a.x;
    }

    // H = relu(cfg@W1+b1), 1024 outputs, 2/thread, stored duplicated {h,h}
    #pragma unroll
    for (int q = 0; q < 2; q++) {
        const int m  = q * 512 + tid;
        const int ln = m >> 6;
        const int o  = m & 63;
        float acc = b1[o];
        const int* crow = cfg + (n0 + ln) * 32;
        #pragma unroll
        for (int i = 0; i < 32; i++)
            acc = fmaf((float)crow[i], W1[i * HID + o], acc);
        const float h = fmaxf(acc, 0.0f);
        sh_hd[ln * HID + o] = pack2(h, h);
    }
    __syncthreads();

    // --- GEMM main loop: compute from w_buf[jq&1], stage jq+1 ahead ---
    unsigned long long acc[16];
    #pragma unroll
    for (int q = 0; q < 16; q++) acc[q] = 0ull;

    const int f0  = tid * 8;
    const int wrow = f0 >> 10;
    const int wcol = f0 & 1023;
    const uint32_t wdst0 = (uint32_t)__cvta_generic_to_shared(w_buf + f0);

    #pragma unroll 1
    for (int jq = 0; jq < 16; jq++) {
        if (jq + 1 < 16) {
            const float* srcw = W2 + ((jq + 1) * 4 + wrow) * NVEC + slab * 1024 + wcol;
            const uint32_t d = wdst0 + ((jq + 1) & 1) * 4096 * 4;
            cp_async16(d, srcw);
            cp_async16(d + 16, srcw + 4);
        }
        COMMIT();
        WAITG(1);          // stage jq complete
        __syncthreads();

        const float* wb = w_buf + (jq & 1) * 4096;
        const float4 w0 = *(const float4*)(wb + 0 * 1024 + tk * 4);
        const float4 w1 = *(const float4*)(wb + 1 * 1024 + tk * 4);
        const float4 w2 = *(const float4*)(wb + 2 * 1024 + tk * 4);
        const float4 w3 = *(const float4*)(wb + 3 * 1024 + tk * 4);
        const unsigned long long w0lo = pack2(w0.x, w0.y), w0hi = pack2(w0.z, w0.w);
        const unsigned long long w1lo = pack2(w1.x, w1.y), w1hi = pack2(w1.z, w1.w);
        const unsigned long long w2lo = pack2(w2.x, w2.y), w2hi = pack2(w2.z, w2.w);
        const unsigned long long w3lo = pack2(w3.x, w3.y), w3hi = pack2(w3.z, w3.w);
        const int j0 = jq * 4;

        #pragma unroll
        for (int s = 0; s < 8; s++) {
            const int sn = sbase + s;
            const ulonglong2 hd01 = *(const ulonglong2*)(sh_hd + sn * HID + j0);
            const ulonglong2 hd23 = *(const ulonglong2*)(sh_hd + sn * HID + j0 + 2);
            unsigned long long a0 = acc[s * 2 + 0];
            unsigned long long a1 = acc[s * 2 + 1];
            a0 = fma2(hd01.x, w0lo, a0);  a1 = fma2(hd01.x, w0hi, a1);
            a0 = fma2(hd01.y, w1lo, a0);  a1 = fma2(hd01.y, w1hi, a1);
            a0 = fma2(hd23.x, w2lo, a0);  a1 = fma2(hd23.x, w2hi, a1);
            a0 = fma2(hd23.y, w3lo, a0);  a1 = fma2(hd23.y, w3hi, a1);
            acc[s * 2 + 0] = a0;
            acc[s * 2 + 1] = a1;
        }
        __syncthreads();   // all reads of w_buf[jq&1] done before restage
    }

    // Epilogue: add s-product, write bt (4 k per thread, 8 samples)
    const int idx = tk * 4;
    const int i  = idx >> 6;
    const int j  = (idx >> 2) & 15;
    const int l = i >> 2, L = i & 3, r = j >> 2, R = j & 3;
    const float4 bk  = *(const float4*)(b2 + k4);
    const float  eta = 0.001f;

    if (!isTop) {
        #pragma unroll
        for (int s = 0; s < 8; s++) {
            const int sn = sbase + s;
            float4 cr;
            unpack2(acc[s * 2 + 0], cr.x, cr.y);
            unpack2(acc[s * 2 + 1], cr.z, cr.w);
            cr.x += bk.x; cr.y += bk.y; cr.z += bk.z; cr.w += bk.w;

            const float* sa = sh_s + sn * 512;        // s0 slice
            const float* sb = sh_s + sn * 512 + 256;  // s1 slice
            const float4  a0 = *(const float4*)(sa + l * 64 + r * 16);
            const float4* b4 = (const float4*)(sb + L * 64 + R * 16);
            const float4 b0 = b4[0], b1v = b4[1], b2v = b4[2], b3v = b4[3];
            float4 o4;
            o4.x = fmaf(a0.x, b0.x, fmaf(a0.y, b1v.x, fmaf(a0.z, b2v.x, fmaf(a0.w, b3v.x, eta * cr.x))));
            o4.y = fmaf(a0.x, b0.y, fmaf(a0.y, b1v.y, fmaf(a0.z, b2v.y, fmaf(a0.w, b3v.y, eta * cr.y))));
            o4.z = fmaf(a0.x, b0.z, fmaf(a0.y, b1v.z, fmaf(a0.z, b2v.z, fmaf(a0.w, b3v.z, eta * cr.z))));
            o4.w = fmaf(a0.x, b0.w, fmaf(a0.y, b1v.w, fmaf(a0.z, b2v.w, fmaf(a0.w, b3v.w, eta * cr.w))));
            *(float4*)(g_bt + (n0 + sn) * NVEC + k4) = o4;
        }
    } else {
        #pragma unroll
        for (int s = 0; s < 8; s++) {
            const int sn = sbase + s;
            float4 cr;
            unpack2(acc[s * 2 + 0], cr.x, cr.y);
            unpack2(acc[s * 2 + 1], cr.z, cr.w);
            cr.x += bk.x; cr.y += bk.y; cr.z += bk.z; cr.w += bk.w;

            const float* sa = sh_s + sn * 512;        // s2 slice
            const float* sb = sh_s + sn * 512 + 256;  // s3 slice
            const float4* c4 = (const float4*)(sa + l * 64 + r * 16);
            const float4 c0 = c4[0], c1 = c4[1], c2 = c4[2], c3 = c4[3];
            const float e0 = sb[L * 64 + R * 16 + 0];
            const float e1 = sb[L * 64 + R * 16 + 4];
            const float e2 = sb[L * 64 + R * 16 + 8];
            const float e3 = sb[L * 64 + R * 16 + 12];
            float4 o4;
            o4.x = fmaf(c0.x, e0, fmaf(c0.y, e1, fmaf(c0.z, e2, fmaf(c0.w, e3, eta * cr.x))));
            o4.y = fmaf(c1.x, e0, fmaf(c1.y, e1, fmaf(c1.z, e2, fmaf(c1.w, e3, eta * cr.y))));
            o4.z = fmaf(c2.x, e0, fmaf(c2.y, e1, fmaf(c2.z, e2, fmaf(c2.w, e3, eta * cr.z))));
            o4.w = fmaf(c3.x, e0, fmaf(c3.y, e1, fmaf(c3.z, e2, fmaf(c3.w, e3, eta * cr.w))));
            *(float4*)(g_bt + (n0 + sn) * NVEC + k4) = o4;
        }
    }
}

// ---------------------------------------------------------------------------
// Kernel B: scan. 128 blocks x 512 threads. ALL 8 tiles prefetched upfront
// (64 KB dynamic smem, one commit group per tile, progressive waits).
// FFMA2 datapath; v duplicated {v,v}; fully unrolled x-loop.
// ---------------------------------------------------------------------------
#define B_SMEM_FLOATS (8 * 2048 + 1024 + 1024)   // buf | sh_t | vd(512 u64=1024 f)

__global__ void __launch_bounds__(512) scan_kernel(float* __restrict__ out)
{
    extern __shared__ float sm[];
    float* buf  = sm;                                   // 8 tiles x 2048 [bot|top]
    float* sh_t = sm + 16384;                           // 1024
    unsigned long long* sh_vd = (unsigned long long*)(sm + 17408);  // 2 x 256

    const int n   = blockIdx.x;
    const int tid = threadIdx.x;
    const float* src = g_bt + n * NVEC;

    const int half = tid >> 8;
    const int e4   = (tid & 255) * 4;
    const uint32_t dst0 = (uint32_t)__cvta_generic_to_shared(buf + half * 1024 + e4);

    // Prefetch all 8 tiles, one group each
    #pragma unroll
    for (int p = 0; p < 8; p++) {
        cp_async16(dst0 + p * 2048 * 4, src + p * 1024 + half * 8192 + e4);
        COMMIT();
    }

    if (tid < 256) {
        const float v = (tid == 0) ? 1.0f : 0.0f;
        sh_vd[tid] = pack2(v, v);
    }

    const int w    = tid >> 5;
    const int lane = tid & 31;
    const int I15  = lane & 15;
    const int ih   = lane >> 4;

    #pragma unroll
    for (int x = 0; x < 8; x++) {
        // progressive wait: tiles 0..x complete  <=>  pending <= 7-x
        if      (x == 0) WAITG(7);
        else if (x == 1) WAITG(6);
        else if (x == 2) WAITG(5);
        else if (x == 3) WAITG(4);
        else if (x == 4) WAITG(3);
        else if (x == 5) WAITG(2);
        else if (x == 6) WAITG(1);
        else             WAITG(0);
        __syncthreads();   // tile x visible to all; prev v visible

        const float* bt = buf + x * 2048;
        const float* tp = bt + 1024;
        const unsigned long long* vcur  = sh_vd + (x & 1) * 256;
        unsigned long long*       vnext = sh_vd + ((x & 1) ^ 1) * 256;

        // step1: t[I,U] = sum_i v[i,I] * bot[i*64 + w*4 + U]
        {
            unsigned long long a01 = 0ull, a23 = 0ull;
            #pragma unroll
            for (int it = 0; it < 8; it++) {
                const int i = ih * 8 + it;
                const ulonglong2 bb = *(const ulonglong2*)(bt + i * 64 + w * 4);
                const unsigned long long vv = vcur[i * 16 + I15];
                a01 = fma2(bb.x, vv, a01);
                a23 = fma2(bb.y, vv, a23);
            }
            float t0, t1, t2, t3;
            unpack2(a01, t0, t1);
            unpack2(a23, t2, t3);
            t0 += __shfl_xor_sync(0xffffffffu, t0, 16);
            t1 += __shfl_xor_sync(0xffffffffu, t1, 16);
            t2 += __shfl_xor_sync(0xffffffffu, t2, 16);
            t3 += __shfl_xor_sync(0xffffffffu, t3, 16);
            if (lane < 16)
                *(float4*)(sh_t + w * 64 + I15 * 4) = make_float4(t0, t1, t2, t3);
        }
        __syncwarp();

        // step2: v'[w,J] = sum_{I,U} t[I,U] * top[I*64 + J*4 + U]
        {
            unsigned long long c01 = 0ull, c23 = 0ull;
            #pragma unroll
            for (int it = 0; it < 8; it++) {
                const int I = ih * 8 + it;
                const ulonglong2 tt = *(const ulonglong2*)(sh_t + w * 64 + I * 4);
                const ulonglong2 pp = *(const ulonglong2*)(tp + I * 64 + I15 * 4);
                c01 = fma2(tt.x, pp.x, c01);
                c23 = fma2(tt.y, pp.y, c23);
            }
            float s0, s1, s2, s3;
            unpack2(c01, s0, s1);
            unpack2(c23, s2, s3);
            float nv = (s0 + s1) + (s2 + s3);
            nv += __shfl_xor_sync(0xffffffffu, nv, 16);
            if (lane < 16) vnext[w * 16 + I15] = pack2(nv, nv);
        }
        __syncthreads();
    }

    if (tid == 0) {
        float a, b;
        unpack2(sh_vd[0], a, b);   // x=7 wrote half 0
        out[n] = a;
    }
}

// ---------------------------------------------------------------------------
extern "C" void kernel_launch(void* const* d_in, const int* in_sizes, int n_in,
                              void* d_out, int out_size)
{
    const int*   cfg = (const int*)  d_in[0];
    const float* A   = (const float*)d_in[1];
    const float* W1  = (const float*)d_in[2];
    const float* b1  = (const float*)d_in[3];
    const float* W2  = (const float*)d_in[4];
    const float* b2  = (const float*)d_in[5];
    float* out = (float*)d_out;

    cudaFuncSetAttribute(fused_gemm_build,
                         cudaFuncAttributeMaxDynamicSharedMemorySize,
                         A_SMEM_FLOATS * 4);
    cudaFuncSetAttribute(scan_kernel,
                         cudaFuncAttributeMaxDynamicSharedMemorySize,
                         B_SMEM_FLOATS * 4);

    fused_gemm_build<<<dim3(16, 8), 512, A_SMEM_FLOATS * 4>>>(cfg, A, W1, b1, W2, b2);
    scan_kernel<<<128, 512, B_SMEM_FLOATS * 4>>>(out);
}

// round 14
// speedup vs baseline: 1.3746x; 1.0156x over previous
#include <cuda_runtime.h>
#include <cuda_bf16.h>
#include <cstdint>

#define HID   64
#define NVEC  16384
#define NB    8192

// NN correction in bf16: corr[n][k] = b2[k] + sum_j h[n][j]*W2[j][k]
__device__ __nv_bfloat16 g_corrb[128 * NVEC];   // 4 MB

// ---- packed fp32x2 helpers ----
__device__ __forceinline__ unsigned long long pack2(float x, float y) {
    unsigned long long d;
    asm("mov.b64 %0, {%1, %2};" : "=l"(d) : "f"(x), "f"(y));
    return d;
}
__device__ __forceinline__ void unpack2(unsigned long long d, float& x, float& y) {
    asm("mov.b64 {%0, %1}, %2;" : "=f"(x), "=f"(y) : "l"(d));
}
__device__ __forceinline__ unsigned long long fma2(unsigned long long a,
                                                   unsigned long long b,
                                                   unsigned long long c) {
    unsigned long long d;
    asm("fma.rn.f32x2 %0, %1, %2, %3;" : "=l"(d) : "l"(a), "l"(b), "l"(c));
    return d;
}

// ---------------------------------------------------------------------------
// Kernel A: pure GEMM, corr = relu(cfg@W1+b1) @ W2 + b2, written as bf16.
// grid = (32 k-blocks, 8 sample-groups), block = 128 threads (R7 config —
// fastest measured A variant). Thread owns 4 consecutive k for 16 samples.
// ---------------------------------------------------------------------------
__global__ void __launch_bounds__(128) nn_gemm_kernel(
    const int*   __restrict__ cfg,
    const float* __restrict__ W1,
    const float* __restrict__ b1,
    const float* __restrict__ W2,
    const float* __restrict__ b2)
{
    __shared__ unsigned long long sh_hd[16 * HID];   // 8 KB, {h,h} duplicated
    const int tid = threadIdx.x;
    const int n0  = blockIdx.y * 16;
    const int k4  = blockIdx.x * 512 + tid * 4;

    // H for 16 samples (1024 outputs, 8/thread), stored duplicated
    #pragma unroll
    for (int s8 = 0; s8 < 8; s8++) {
        const int m  = s8 * 128 + tid;
        const int ln = m >> 6;
        const int o  = m & 63;
        float acc = b1[o];
        const int* crow = cfg + (n0 + ln) * 32;
        #pragma unroll
        for (int i = 0; i < 32; i++)
            acc = fmaf((float)crow[i], W1[i * HID + o], acc);
        const float h = fmaxf(acc, 0.0f);
        sh_hd[ln * HID + o] = pack2(h, h);
    }
    __syncthreads();

    unsigned long long acc[32];   // acc[s*2 + p], p = k-pair
    #pragma unroll
    for (int q = 0; q < 32; q++) acc[q] = 0ull;

    #pragma unroll 4
    for (int jq = 0; jq < 16; jq++) {
        const int j0 = jq * 4;
        const float4 w0 = *(const float4*)(W2 + (j0 + 0) * NVEC + k4);
        const float4 w1 = *(const float4*)(W2 + (j0 + 1) * NVEC + k4);
        const float4 w2 = *(const float4*)(W2 + (j0 + 2) * NVEC + k4);
        const float4 w3 = *(const float4*)(W2 + (j0 + 3) * NVEC + k4);
        const unsigned long long w0lo = pack2(w0.x, w0.y), w0hi = pack2(w0.z, w0.w);
        const unsigned long long w1lo = pack2(w1.x, w1.y), w1hi = pack2(w1.z, w1.w);
        const unsigned long long w2lo = pack2(w2.x, w2.y), w2hi = pack2(w2.z, w2.w);
        const unsigned long long w3lo = pack2(w3.x, w3.y), w3hi = pack2(w3.z, w3.w);

        #pragma unroll
        for (int s = 0; s < 16; s++) {
            const ulonglong2 hd01 = *(const ulonglong2*)(sh_hd + s * HID + j0);
            const ulonglong2 hd23 = *(const ulonglong2*)(sh_hd + s * HID + j0 + 2);
            unsigned long long a0 = acc[s * 2 + 0];
            unsigned long long a1 = acc[s * 2 + 1];
            a0 = fma2(hd01.x, w0lo, a0);  a1 = fma2(hd01.x, w0hi, a1);
            a0 = fma2(hd01.y, w1lo, a0);  a1 = fma2(hd01.y, w1hi, a1);
            a0 = fma2(hd23.x, w2lo, a0);  a1 = fma2(hd23.x, w2hi, a1);
            a0 = fma2(hd23.y, w3lo, a0);  a1 = fma2(hd23.y, w3hi, a1);
            acc[s * 2 + 0] = a0;
            acc[s * 2 + 1] = a1;
        }
    }

    const float4 bk = *(const float4*)(b2 + k4);
    #pragma unroll
    for (int s = 0; s < 16; s++) {
        float4 r;
        unpack2(acc[s * 2 + 0], r.x, r.y);
        unpack2(acc[s * 2 + 1], r.z, r.w);
        r.x += bk.x; r.y += bk.y; r.z += bk.z; r.w += bk.w;
        __nv_bfloat162 lo = __floats2bfloat162_rn(r.x, r.y);
        __nv_bfloat162 hi = __floats2bfloat162_rn(r.z, r.w);
        uint2 pk;
        pk.x = *reinterpret_cast<unsigned*>(&lo);
        pk.y = *reinterpret_cast<unsigned*>(&hi);
        *(uint2*)(g_corrb + (n0 + s) * NVEC + k4) = pk;   // 8B coalesced
    }
}

// ---------------------------------------------------------------------------
// Kernel B: gather + build bot/top (corr read as bf16) + FFMA2 scan.
// 128 blocks (1/sample) x 512 threads.
// smem floats: bot[8192] | top[8192] | s[8192] | t[1024] | vd (512 u64)
// ---------------------------------------------------------------------------
#define B_SMEM_FLOATS (8192 + 8192 + 8192 + 1024 + 1024)

__global__ void __launch_bounds__(512) contract_scan(
    const int*   __restrict__ cfg,
    const float* __restrict__ A,
    float*       __restrict__ out)
{
    extern __shared__ float sm[];
    float* sh_bot = sm;
    float* sh_top = sm + 8192;
    float* sh_s   = sm + 16384;
    float* sh_t   = sm + 24576;
    unsigned long long* sh_vd = (unsigned long long*)(sm + 25600);  // 2 x 256
    __shared__ int sh_c[32];

    const int n   = blockIdx.x;
    const int tid = threadIdx.x;

    if (tid < 32) sh_c[tid] = cfg[n * 32 + tid];
    __syncthreads();

    // Gather s: A flat = m*2 + phys  (L2-resident after first wave)
    const float2* A2 = (const float2*)A;
    #pragma unroll
    for (int q = 0; q < 16; q++) {
        const int m = q * 512 + tid;
        const float2 a = A2[m];
        sh_s[m] = sh_c[m >> 8] ? a.y : a.x;
    }
    if (tid < 256) {
        const float v = (tid == 0) ? 1.0f : 0.0f;
        sh_vd[tid] = pack2(v, v);
    }
    __syncthreads();

    const __nv_bfloat16* corr = g_corrb + n * NVEC;
    const float eta = 0.001f;

    // Build ALL bot2/top2 (+ bf16 corr), 2048 groups of 4 U, 4/thread
    #pragma unroll
    for (int q = 0; q < 4; q++) {
        const int g = q * 512 + tid;
        const int x = g >> 8;
        const int i = (g >> 4) & 15;
        const int j = g & 15;
        const int l = i >> 2, L = i & 3;
        const int r = j >> 2, R = j & 3;
        const float* s0 = sh_s + (x * 4 + 0) * 256;
        const float* s1 = sh_s + (x * 4 + 1) * 256;
        const float* s2 = sh_s + (x * 4 + 2) * 256;
        const float* s3 = sh_s + (x * 4 + 3) * 256;

        const float4  a0 = *(const float4*)(s0 + l * 64 + r * 16);
        const float4* b4 = (const float4*)(s1 + L * 64 + R * 16);
        const float4 b0 = b4[0], b1v = b4[1], b2v = b4[2], b3v = b4[3];
        float4 bo;
        bo.x = fmaf(a0.x, b0.x, fmaf(a0.y, b1v.x, fmaf(a0.z, b2v.x, a0.w * b3v.x)));
        bo.y = fmaf(a0.x, b0.y, fmaf(a0.y, b1v.y, fmaf(a0.z, b2v.y, a0.w * b3v.y)));
        bo.z = fmaf(a0.x, b0.z, fmaf(a0.y, b1v.z, fmaf(a0.z, b2v.z, a0.w * b3v.z)));
        bo.w = fmaf(a0.x, b0.w, fmaf(a0.y, b1v.w, fmaf(a0.z, b2v.w, a0.w * b3v.w)));

        const float4* c4 = (const float4*)(s2 + l * 64 + r * 16);
        const float4 c0 = c4[0], c1 = c4[1], c2 = c4[2], c3 = c4[3];
        const float e0 = s3[L * 64 + R * 16 + 0];
        const float e1 = s3[L * 64 + R * 16 + 4];
        const float e2 = s3[L * 64 + R * 16 + 8];
        const float e3 = s3[L * 64 + R * 16 + 12];
        float4 to;
        to.x = fmaf(c0.x, e0, fmaf(c0.y, e1, fmaf(c0.z, e2, c0.w * e3)));
        to.y = fmaf(c1.x, e0, fmaf(c1.y, e1, fmaf(c1.z, e2, c1.w * e3)));
        to.z = fmaf(c2.x, e0, fmaf(c2.y, e1, fmaf(c2.z, e2, c2.w * e3)));
        to.w = fmaf(c3.x, e0, fmaf(c3.y, e1, fmaf(c3.z, e2, c3.w * e3)));

        const int mbase = x * 1024 + i * 64 + j * 4;

        const uint2 cbp = *(const uint2*)(corr + mbase);
        const uint2 ctp = *(const uint2*)(corr + NB + mbase);
        const __nv_bfloat162 cb0 = *reinterpret_cast<const __nv_bfloat162*>(&cbp.x);
        const __nv_bfloat162 cb1 = *reinterpret_cast<const __nv_bfloat162*>(&cbp.y);
        const __nv_bfloat162 ct0 = *reinterpret_cast<const __nv_bfloat162*>(&ctp.x);
        const __nv_bfloat162 ct1 = *reinterpret_cast<const __nv_bfloat162*>(&ctp.y);
        const float2 cb01 = __bfloat1622float2(cb0);
        const float2 cb23 = __bfloat1622float2(cb1);
        const float2 ct01 = __bfloat1622float2(ct0);
        const float2 ct23 = __bfloat1622float2(ct1);

        float4 ob, ot;
        ob.x = fmaf(eta, cb01.x, bo.x); ob.y = fmaf(eta, cb01.y, bo.y);
        ob.z = fmaf(eta, cb23.x, bo.z); ob.w = fmaf(eta, cb23.y, bo.w);
        ot.x = fmaf(eta, ct01.x, to.x); ot.y = fmaf(eta, ct01.y, to.y);
        ot.z = fmaf(eta, ct23.x, to.z); ot.w = fmaf(eta, ct23.y, to.w);
        *(float4*)(sh_bot + mbase) = ob;
        *(float4*)(sh_top + mbase) = ot;
    }
    __syncthreads();

    // Scan: proven FFMA2 datapath, 1 block barrier per x
    const int w    = tid >> 5;
    const int lane = tid & 31;
    const int I15  = lane & 15;
    const int ih   = lane >> 4;

    #pragma unroll 1
    for (int x = 0; x < 8; x++) {
        const float* bt = sh_bot + x * 1024;
        const float* tp = sh_top + x * 1024;
        const unsigned long long* vcur  = sh_vd + (x & 1) * 256;
        unsigned long long*       vnext = sh_vd + ((x & 1) ^ 1) * 256;

        // step1: t[I,U] = sum_i v[i,I] * bot[i*64 + w*4 + U]
        {
            unsigned long long a01 = 0ull, a23 = 0ull;
            #pragma unroll
            for (int it = 0; it < 8; it++) {
                const int i = ih * 8 + it;
                const ulonglong2 bb = *(const ulonglong2*)(bt + i * 64 + w * 4);
                const unsigned long long vv = vcur[i * 16 + I15];
                a01 = fma2(bb.x, vv, a01);
                a23 = fma2(bb.y, vv, a23);
            }
            float t0, t1, t2, t3;
            unpack2(a01, t0, t1);
            unpack2(a23, t2, t3);
            t0 += __shfl_xor_sync(0xffffffffu, t0, 16);
            t1 += __shfl_xor_sync(0xffffffffu, t1, 16);
            t2 += __shfl_xor_sync(0xffffffffu, t2, 16);
            t3 += __shfl_xor_sync(0xffffffffu, t3, 16);
            if (lane < 16)
                *(float4*)(sh_t + w * 64 + I15 * 4) = make_float4(t0, t1, t2, t3);
        }
        __syncwarp();

        // step2: v'[w,J] = sum_{I,U} t[I,U] * top[I*64 + J*4 + U]
        {
            unsigned long long c01 = 0ull, c23 = 0ull;
            #pragma unroll
            for (int it = 0; it < 8; it++) {
                const int I = ih * 8 + it;
                const ulonglong2 tt = *(const ulonglong2*)(sh_t + w * 64 + I * 4);
                const ulonglong2 pp = *(const ulonglong2*)(tp + I * 64 + I15 * 4);
                c01 = fma2(tt.x, pp.x, c01);
                c23 = fma2(tt.y, pp.y, c23);
            }
            float s0, s1, s2, s3;
            unpack2(c01, s0, s1);
            unpack2(c23, s2, s3);
            float nv = (s0 + s1) + (s2 + s3);
            nv += __shfl_xor_sync(0xffffffffu, nv, 16);
            if (lane < 16) vnext[w * 16 + I15] = pack2(nv, nv);
        }
        __syncthreads();
    }

    if (tid == 0) {
        float a, b;
        unpack2(sh_vd[0], a, b);   // x=7 wrote half 0
        out[n] = a;
    }
}

// ---------------------------------------------------------------------------
extern "C" void kernel_launch(void* const* d_in, const int* in_sizes, int n_in,
                              void* d_out, int out_size)
{
    const int*   cfg = (const int*)  d_in[0];
    const float* A   = (const float*)d_in[1];
    const float* W1  = (const float*)d_in[2];
    const float* b1  = (const float*)d_in[3];
    const float* W2  = (const float*)d_in[4];
    const float* b2  = (const float*)d_in[5];
    float* out = (float*)d_out;

    cudaFuncSetAttribute(contract_scan,
                         cudaFuncAttributeMaxDynamicSharedMemorySize,
                         B_SMEM_FLOATS * 4);

    nn_gemm_kernel<<<dim3(32, 8), 128>>>(cfg, W1, b1, W2, b2);
    contract_scan<<<128, 512, B_SMEM_FLOATS * 4>>>(cfg, A, out);
}